// round 9
// baseline (speedup 1.0000x reference)
#include <cuda_runtime.h>
#include <cuda_bf16.h>

// out[b,h,i,j] = in[b,h,i,j] + slope[h] * (j - (S-1)),  slope[h] = 2^(-0.5*(h+1))
// Shape: (2, 16, 2048, 2048) fp32. Pure HBM-streaming elementwise add.
//
// R9 (final): best-measured config (R8) + MUFU-free slope.
//   512-thread blocks, VPT8=2 (16 floats/thread), 16384 blocks; each block
//   covers one contiguous 64KB span = 4 rows of one head plane (h uniform).
//   256-bit accesses: .cs loads (read-once), .wb stores (L2 write batching).
//   Measured: 6.83 TB/s, DRAM 86.2% — HBM R/W-turnaround roofline.

static constexpr int SEQ = 2048;
static constexpr unsigned int ROW_MASK8 = (SEQ / 8) - 1;  // v8 slots per row
static constexpr int HEAD_SHIFT8 = 22 - 3;   // head plane = 2^19 v8 slots
static constexpr int HEAD_MASK = 15;
static constexpr int VPT8 = 2;               // 32B slots per thread
static constexpr unsigned int BLOCK = 512;

struct F8 { float a0,a1,a2,a3,a4,a5,a6,a7; };

__device__ __forceinline__ F8 ldg_cs_v8(const float* p) {
    F8 r;
    asm volatile("ld.global.cs.v8.f32 {%0,%1,%2,%3,%4,%5,%6,%7}, [%8];"
                 : "=f"(r.a0), "=f"(r.a1), "=f"(r.a2), "=f"(r.a3),
                   "=f"(r.a4), "=f"(r.a5), "=f"(r.a6), "=f"(r.a7)
                 : "l"(p));
    return r;
}

__device__ __forceinline__ void stg_wb_v8(float* p, const F8& r) {
    asm volatile("st.global.v8.f32 [%0], {%1,%2,%3,%4,%5,%6,%7,%8};"
                 :: "l"(p),
                    "f"(r.a0), "f"(r.a1), "f"(r.a2), "f"(r.a3),
                    "f"(r.a4), "f"(r.a5), "f"(r.a6), "f"(r.a7)
                 : "memory");
}

__global__ void __launch_bounds__(512)
alibi_add_kernel(const float* __restrict__ in, float* __restrict__ out) {
    unsigned int base = blockIdx.x * (BLOCK * VPT8) + threadIdx.x;

    // Block spans 1024 v8-slots = 4 full rows of one head plane -> h uniform.
    int n = (int)((base >> HEAD_SHIFT8) & HEAD_MASK) + 1;   // 1..16
    // slope = 2^(-n/2) = 2^(-(n>>1)) * (n odd ? 2^-0.5 : 1), MUFU-free & exact.
    float p2   = __uint_as_float((unsigned)(127 - (n >> 1)) << 23);
    float slope = (n & 1) ? p2 * 0.70710678118654752f : p2;

    F8 v[VPT8];
#pragma unroll
    for (int k = 0; k < VPT8; k++) {
        v[k] = ldg_cs_v8(in + (unsigned long long)(base + k * BLOCK) * 8ull);
    }

#pragma unroll
    for (int k = 0; k < VPT8; k++) {
        unsigned int slot = base + k * BLOCK;
        int j8 = (int)(slot & ROW_MASK8);
        float d0 = (float)(j8 * 8 - (SEQ - 1));

        F8 r = v[k];
        r.a0 = fmaf(slope, d0,        r.a0);
        r.a1 = fmaf(slope, d0 + 1.0f, r.a1);
        r.a2 = fmaf(slope, d0 + 2.0f, r.a2);
        r.a3 = fmaf(slope, d0 + 3.0f, r.a3);
        r.a4 = fmaf(slope, d0 + 4.0f, r.a4);
        r.a5 = fmaf(slope, d0 + 5.0f, r.a5);
        r.a6 = fmaf(slope, d0 + 6.0f, r.a6);
        r.a7 = fmaf(slope, d0 + 7.0f, r.a7);
        stg_wb_v8(out + (unsigned long long)slot * 8ull, r);
    }
}

extern "C" void kernel_launch(void* const* d_in, const int* in_sizes, int n_in,
                              void* d_out, int out_size) {
    const float* in = (const float*)d_in[0];
    float* out = (float*)d_out;
    unsigned int n8 = (unsigned int)(out_size / 8);       // 16777216 v8 slots
    unsigned int grid = n8 / (BLOCK * VPT8);              // 16384 blocks (exact)
    alibi_add_kernel<<<grid, BLOCK>>>(in, out);
}

// round 10
// speedup vs baseline: 1.0037x; 1.0037x over previous
#include <cuda_runtime.h>
#include <cuda_bf16.h>

// out[b,h,i,j] = in[b,h,i,j] + slope[h] * (j - (S-1)),  slope[h] = 2^(-0.5*(h+1))
// Shape: (2, 16, 2048, 2048) fp32. Pure HBM-streaming elementwise add.
//
// FINAL (R10): converged roofline configuration.
//   512-thread blocks, VPT8=2 (16 floats/thread), 16384 blocks; each block
//   covers one contiguous 64KB span = 4 rows of one head plane (h uniform).
//   256-bit accesses: .cs loads (read-once), .wb stores (L2 write batching).
//   MUFU-free exact slope. Stores batched after compute.
//   Measured across R5-R9: 6.83 TB/s, DRAM-active 86.2% — the HBM mixed
//   read/write turnaround ceiling for this part. All compute pipes <7%.

static constexpr int SEQ = 2048;
static constexpr unsigned int ROW_MASK8 = (SEQ / 8) - 1;  // v8 slots per row
static constexpr int HEAD_SHIFT8 = 22 - 3;   // head plane = 2^19 v8 slots
static constexpr int HEAD_MASK = 15;
static constexpr int VPT8 = 2;               // 32B slots per thread
static constexpr unsigned int BLOCK = 512;

struct F8 { float a0,a1,a2,a3,a4,a5,a6,a7; };

__device__ __forceinline__ F8 ldg_cs_v8(const float* p) {
    F8 r;
    asm volatile("ld.global.cs.v8.f32 {%0,%1,%2,%3,%4,%5,%6,%7}, [%8];"
                 : "=f"(r.a0), "=f"(r.a1), "=f"(r.a2), "=f"(r.a3),
                   "=f"(r.a4), "=f"(r.a5), "=f"(r.a6), "=f"(r.a7)
                 : "l"(p));
    return r;
}

__device__ __forceinline__ void stg_wb_v8(float* p, const F8& r) {
    asm volatile("st.global.v8.f32 [%0], {%1,%2,%3,%4,%5,%6,%7,%8};"
                 :: "l"(p),
                    "f"(r.a0), "f"(r.a1), "f"(r.a2), "f"(r.a3),
                    "f"(r.a4), "f"(r.a5), "f"(r.a6), "f"(r.a7)
                 : "memory");
}

__global__ void __launch_bounds__(512)
alibi_add_kernel(const float* __restrict__ in, float* __restrict__ out) {
    unsigned int base = blockIdx.x * (BLOCK * VPT8) + threadIdx.x;

    // Block spans 1024 v8-slots = 4 full rows of one head plane -> h uniform.
    int n = (int)((base >> HEAD_SHIFT8) & HEAD_MASK) + 1;   // 1..16
    // slope = 2^(-n/2) = 2^(-(n>>1)) * (n odd ? 2^-0.5 : 1), MUFU-free & exact.
    float p2    = __uint_as_float((unsigned)(127 - (n >> 1)) << 23);
    float slope = (n & 1) ? p2 * 0.70710678118654752f : p2;

    F8 v[VPT8];
#pragma unroll
    for (int k = 0; k < VPT8; k++) {
        v[k] = ldg_cs_v8(in + (unsigned long long)(base + k * BLOCK) * 8ull);
    }

#pragma unroll
    for (int k = 0; k < VPT8; k++) {
        unsigned int slot = base + k * BLOCK;
        int j8 = (int)(slot & ROW_MASK8);
        float d0 = (float)(j8 * 8 - (SEQ - 1));

        v[k].a0 = fmaf(slope, d0,        v[k].a0);
        v[k].a1 = fmaf(slope, d0 + 1.0f, v[k].a1);
        v[k].a2 = fmaf(slope, d0 + 2.0f, v[k].a2);
        v[k].a3 = fmaf(slope, d0 + 3.0f, v[k].a3);
        v[k].a4 = fmaf(slope, d0 + 4.0f, v[k].a4);
        v[k].a5 = fmaf(slope, d0 + 5.0f, v[k].a5);
        v[k].a6 = fmaf(slope, d0 + 6.0f, v[k].a6);
        v[k].a7 = fmaf(slope, d0 + 7.0f, v[k].a7);
    }

#pragma unroll
    for (int k = 0; k < VPT8; k++) {
        stg_wb_v8(out + (unsigned long long)(base + k * BLOCK) * 8ull, v[k]);
    }
}

extern "C" void kernel_launch(void* const* d_in, const int* in_sizes, int n_in,
                              void* d_out, int out_size) {
    const float* in = (const float*)d_in[0];
    float* out = (float*)d_out;
    unsigned int n8 = (unsigned int)(out_size / 8);       // 16777216 v8 slots
    unsigned int grid = n8 / (BLOCK * VPT8);              // 16384 blocks (exact)
    alibi_add_kernel<<<grid, BLOCK>>>(in, out);
}